// round 1
// baseline (speedup 1.0000x reference)
#include <cuda_runtime.h>
#include <math.h>

#define B_   2
#define S_   2048
#define D_   1024
#define H_   8
#define FFN_ 4096
#define DK_  128
#define VD_  2048
#define DV_  256
#define NT_  (B_*S_)   // 4096 tokens

// ---------------- scratch (static device allocations; harness-safe) -------
__device__ float d_Xn   [B_*S_*D_];
__device__ float d_Q    [B_*H_*S_*DK_];
__device__ float d_K    [B_*H_*S_*DK_];
__device__ float d_Kt   [B_*H_*DK_*S_];
__device__ float d_V    [B_*H_*S_*DV_];
__device__ float d_G    [B_*S_*VD_];
__device__ float d_Y    [B_*H_*S_*DV_];
__device__ float d_gated[B_*S_*VD_];
__device__ float d_X2   [B_*S_*D_];
__device__ float d_h1   [(size_t)B_*S_*FFN_];
__device__ float d_Sc   [(size_t)B_*H_*S_*S_];
__device__ float d_xpt  [S_*64*4];

// ---------------- block reduction ----------------------------------------
template<int NT>
__device__ __forceinline__ float blockSum(float v) {
    __shared__ float sh[NT/32];
    int lane = threadIdx.x & 31;
    int w    = threadIdx.x >> 5;
    #pragma unroll
    for (int o = 16; o > 0; o >>= 1) v += __shfl_xor_sync(0xffffffffu, v, o);
    if (lane == 0) sh[w] = v;
    __syncthreads();
    float tot = 0.f;
    #pragma unroll
    for (int i = 0; i < NT/32; i++) tot += sh[i];
    __syncthreads();
    return tot;
}

// ---------------- generic batched SGEMM (row-major, 128x128x8) -----------
// C[z] = A[z/aDiv] * B[z%bMod]; M,N multiples of 128; K multiple of 8.
__global__ __launch_bounds__(256, 2)
void sgemm_k(const float* __restrict__ A, const float* __restrict__ Bm,
             float* __restrict__ C, int M, int N, int K,
             long long sA, long long sB, long long sC, int aDiv, int bMod)
{
    A  += (long long)(blockIdx.z / aDiv) * sA;
    Bm += (long long)(blockIdx.z % bMod) * sB;
    C  += (long long)blockIdx.z * sC;

    __shared__ float As[8][128];
    __shared__ float Bs[8][128];

    int tid   = threadIdx.x;
    int a_row = tid >> 1;
    int a_col = (tid & 1) << 2;
    int b_row = tid >> 5;
    int b_col = (tid & 31) << 2;
    int trow  = (tid >> 4) << 3;
    int tcol  = (tid & 15) << 3;

    const float* Ap = A  + (long long)(blockIdx.y * 128 + a_row) * K + a_col;
    const float* Bp = Bm + (long long)b_row * N + blockIdx.x * 128 + b_col;

    float acc[8][8];
    #pragma unroll
    for (int i = 0; i < 8; i++)
        #pragma unroll
        for (int j = 0; j < 8; j++) acc[i][j] = 0.f;

    for (int k0 = 0; k0 < K; k0 += 8) {
        float4 av = *(const float4*)(Ap + k0);
        float4 bv = *(const float4*)(Bp + (long long)k0 * N);
        As[a_col + 0][a_row] = av.x;
        As[a_col + 1][a_row] = av.y;
        As[a_col + 2][a_row] = av.z;
        As[a_col + 3][a_row] = av.w;
        *(float4*)&Bs[b_row][b_col] = bv;
        __syncthreads();
        #pragma unroll
        for (int k = 0; k < 8; k++) {
            float ar[8], br[8];
            #pragma unroll
            for (int i = 0; i < 8; i++) ar[i] = As[k][trow + i];
            #pragma unroll
            for (int j = 0; j < 8; j++) br[j] = Bs[k][tcol + j];
            #pragma unroll
            for (int i = 0; i < 8; i++)
                #pragma unroll
                for (int j = 0; j < 8; j++)
                    acc[i][j] = fmaf(ar[i], br[j], acc[i][j]);
        }
        __syncthreads();
    }

    #pragma unroll
    for (int i = 0; i < 8; i++) {
        float* Cp = C + (long long)(blockIdx.y * 128 + trow + i) * N
                      + blockIdx.x * 128 + tcol;
        float4 v0 = make_float4(acc[i][0], acc[i][1], acc[i][2], acc[i][3]);
        float4 v1 = make_float4(acc[i][4], acc[i][5], acc[i][6], acc[i][7]);
        *(float4*)Cp       = v0;
        *((float4*)Cp + 1) = v1;
    }
}

// ---------------- layernorm (D=1024, 256 threads, 4 elems/thread) --------
__global__ void layernorm_k(const float* __restrict__ X, const float* __restrict__ w,
                            const float* __restrict__ b, float* __restrict__ out)
{
    size_t tok = blockIdx.x;
    const float* x = X + tok * D_;
    float vals[4];
    float s = 0.f;
    #pragma unroll
    for (int i = 0; i < 4; i++) { vals[i] = x[threadIdx.x + i*256]; s += vals[i]; }
    float mean = blockSum<256>(s) * (1.0f / D_);
    float vs = 0.f;
    #pragma unroll
    for (int i = 0; i < 4; i++) { float d = vals[i] - mean; vs += d*d; }
    float var = blockSum<256>(vs) * (1.0f / D_);
    float inv = rsqrtf(var + 1e-5f);
    float* o = out + tok * D_;
    #pragma unroll
    for (int i = 0; i < 4; i++) {
        int c = threadIdx.x + i*256;
        o[c] = (vals[i] - mean) * inv * w[c] + b[c];
    }
}

// ---------------- xpos table (fp64 trig for accuracy) ---------------------
__global__ void xpos_table_k(float* __restrict__ tab)
{
    int idx = blockIdx.x * 256 + threadIdx.x;
    if (idx >= S_ * 64) return;
    int i = idx & 63;
    int s = idx >> 6;
    double pos = (double)s;
    double sv  = (2.0*i + 0.4*128.0) / (1.4*128.0);
    double scl = pow(sv, pos / 512.0);
    float inv_freq_f = (float)pow(10000.0, -(double)i / 64.0);
    float ang_f = (float)s * inv_freq_f;       // mimic fp32 argument as in ref
    double ang = (double)ang_f;
    double sn = sin(ang), cs = cos(ang);
    tab[idx*4 + 0] = (float)(cs * scl);   // cos for Q
    tab[idx*4 + 1] = (float)(sn * scl);   // sin for Q
    tab[idx*4 + 2] = (float)(cs / scl);   // cos for K (downscale)
    tab[idx*4 + 3] = (float)(sn / scl);   // sin for K
}

// ---------------- apply xpos rotary to Q and K in place -------------------
__global__ void xpos_apply_k(float* __restrict__ Q, float* __restrict__ K,
                             const float* __restrict__ tab)
{
    long long idx = (long long)blockIdx.x * 256 + threadIdx.x;
    if (idx >= (long long)B_*H_*S_*64) return;
    int i = (int)(idx & 63);
    long long r = idx >> 6;
    int s = (int)(r % S_);
    long long base = r * 128 + 2*i;
    const float* t = tab + ((long long)s*64 + i) * 4;
    float cq = t[0], sq = t[1], ck = t[2], sk = t[3];
    float q1 = Q[base], q2 = Q[base+1];
    Q[base]   = q1*cq - q2*sq;
    Q[base+1] = q2*cq + q1*sq;
    float k1 = K[base], k2 = K[base+1];
    K[base]   = k1*ck - k2*sk;
    K[base+1] = k2*ck + k1*sk;
}

// ---------------- transpose per batch (rows x cols -> cols x rows) --------
__global__ void transpose_k(const float* __restrict__ in, float* __restrict__ out,
                            int rows, int cols)
{
    __shared__ float tile[32][33];
    const float* ib = in  + (long long)blockIdx.z * rows * cols;
    float*       ob = out + (long long)blockIdx.z * rows * cols;
    int r0 = blockIdx.x * 32, c0 = blockIdx.y * 32;
    int tx = threadIdx.x, ty = threadIdx.y;
    #pragma unroll
    for (int j = 0; j < 32; j += 8)
        tile[ty + j][tx] = ib[(long long)(r0 + ty + j) * cols + c0 + tx];
    __syncthreads();
    #pragma unroll
    for (int j = 0; j < 32; j += 8)
        ob[(long long)(c0 + ty + j) * rows + r0 + tx] = tile[tx][ty + j];
}

// ---------------- causal decay mask --------------------------------------
__global__ void decay_k(float* __restrict__ Sc)
{
    size_t idx = (size_t)blockIdx.x * 256 + threadIdx.x;
    if (idx >= (size_t)B_*H_*S_*S_) return;
    int t = (int)(idx & (S_ - 1));
    size_t r = idx >> 11;
    int s = (int)(r & (S_ - 1));
    int h = (int)((r >> 11) & (H_ - 1));
    if (t > s) { Sc[idx] = 0.f; return; }
    const float l32  = -3.4657359027997265f;   // ln(1/32)
    const float l512 = -6.2383246250395075f;   // ln(1/512)
    float frac = (float)h * (1.0f / 7.0f);
    float g = 1.0f - expf(l32 + (l512 - l32) * frac);
    float w = exp2f((float)(s - t) * log2f(g));
    Sc[idx] *= w;
}

// ---------------- groupnorm (per b,s,h over DV) + silu gate ---------------
__global__ void gnorm_gate_k(const float* __restrict__ Y, const float* __restrict__ G,
                             const float* __restrict__ w, const float* __restrict__ bb,
                             float* __restrict__ out)
{
    int h = blockIdx.x % H_;
    int s = (blockIdx.x / H_) % S_;
    int b = blockIdx.x / (H_ * S_);
    int v = threadIdx.x;

    size_t yoff = (((size_t)(b*H_ + h)) * S_ + s) * DV_ + v;
    float y = Y[yoff];
    float mean = blockSum<256>(y) * (1.0f / DV_);
    float d = y - mean;
    float var = blockSum<256>(d*d) * (1.0f / DV_);
    float yn = d * rsqrtf(var + 1e-5f);

    int col = h*DV_ + v;
    size_t goff = ((size_t)(b*S_ + s)) * VD_ + col;
    float g = G[goff];
    float gate = g / (1.0f + expf(-g));   // g * sigmoid(g)
    out[goff] = gate * (yn * w[col] + bb[col]);
}

// ---------------- elementwise helpers -------------------------------------
__global__ void add_k(float* __restrict__ a, const float* __restrict__ b, size_t n)
{
    size_t idx = (size_t)blockIdx.x * 256 + threadIdx.x;
    if (idx < n) a[idx] += b[idx];
}

__global__ void biasgelu_k(float* __restrict__ h, const float* __restrict__ b1)
{
    size_t idx = (size_t)blockIdx.x * 256 + threadIdx.x;
    if (idx >= (size_t)NT_ * FFN_) return;
    float x = h[idx] + b1[idx & (FFN_ - 1)];
    h[idx] = 0.5f * x * (1.0f + erff(x * 0.70710678118654752f));
}

__global__ void final_k(float* __restrict__ out, const float* __restrict__ b2,
                        const float* __restrict__ X2)
{
    size_t idx = (size_t)blockIdx.x * 256 + threadIdx.x;
    if (idx >= (size_t)NT_ * D_) return;
    out[idx] = out[idx] + b2[idx & (D_ - 1)] + X2[idx];
}

// ---------------- host launcher -------------------------------------------
extern "C" void kernel_launch(void* const* d_in, const int* in_sizes, int n_in,
                              void* d_out, int out_size)
{
    (void)in_sizes; (void)n_in; (void)out_size;
    const float* X      = (const float*)d_in[0];
    const float* Wq     = (const float*)d_in[1];
    const float* Wk     = (const float*)d_in[2];
    const float* Wv     = (const float*)d_in[3];
    const float* W_G    = (const float*)d_in[4];
    const float* W_O    = (const float*)d_in[5];
    const float* gn_w   = (const float*)d_in[6];
    const float* gn_b   = (const float*)d_in[7];
    const float* ln1_w  = (const float*)d_in[8];
    const float* ln1_b  = (const float*)d_in[9];
    const float* ln2_w  = (const float*)d_in[10];
    const float* ln2_b  = (const float*)d_in[11];
    const float* ffn_w1 = (const float*)d_in[12];
    const float* ffn_b1 = (const float*)d_in[13];
    const float* ffn_w2 = (const float*)d_in[14];
    const float* ffn_b2 = (const float*)d_in[15];
    float* out = (float*)d_out;

    float *Xn, *Q, *K, *Kt, *V, *G, *Y, *gated, *X2, *h1, *Sc, *xpt;
    cudaGetSymbolAddress((void**)&Xn,    d_Xn);
    cudaGetSymbolAddress((void**)&Q,     d_Q);
    cudaGetSymbolAddress((void**)&K,     d_K);
    cudaGetSymbolAddress((void**)&Kt,    d_Kt);
    cudaGetSymbolAddress((void**)&V,     d_V);
    cudaGetSymbolAddress((void**)&G,     d_G);
    cudaGetSymbolAddress((void**)&Y,     d_Y);
    cudaGetSymbolAddress((void**)&gated, d_gated);
    cudaGetSymbolAddress((void**)&X2,    d_X2);
    cudaGetSymbolAddress((void**)&h1,    d_h1);
    cudaGetSymbolAddress((void**)&Sc,    d_Sc);
    cudaGetSymbolAddress((void**)&xpt,   d_xpt);

    // 1) ln1
    layernorm_k<<<NT_, 256>>>(X, ln1_w, ln1_b, Xn);

    // 2) projections: Q,K (per-head), V (per-head), G (full)
    sgemm_k<<<dim3(1, 16, B_*H_), 256>>>(Xn, Wq, Q, S_, DK_, D_,
        (long long)S_*D_, (long long)D_*DK_, (long long)S_*DK_, H_, H_);
    sgemm_k<<<dim3(1, 16, B_*H_), 256>>>(Xn, Wk, K, S_, DK_, D_,
        (long long)S_*D_, (long long)D_*DK_, (long long)S_*DK_, H_, H_);
    sgemm_k<<<dim3(2, 16, B_*H_), 256>>>(Xn, Wv, V, S_, DV_, D_,
        (long long)S_*D_, (long long)D_*DV_, (long long)S_*DV_, H_, H_);
    sgemm_k<<<dim3(16, 32, 1), 256>>>(Xn, W_G, G, NT_, VD_, D_, 0, 0, 0, 1, 1);

    // 3) xpos rotary
    xpos_table_k<<<(S_*64 + 255)/256, 256>>>(xpt);
    xpos_apply_k<<<(B_*H_*S_*64)/256, 256>>>(Q, K, xpt);

    // 4) retention: scores = Q K^T (via K transpose), decay mask, Y = scores V
    transpose_k<<<dim3(S_/32, DK_/32, B_*H_), dim3(32, 8)>>>(K, Kt, S_, DK_);
    sgemm_k<<<dim3(16, 16, B_*H_), 256>>>(Q, Kt, Sc, S_, S_, DK_,
        (long long)S_*DK_, (long long)DK_*S_, (long long)S_*S_, 1, B_*H_);
    decay_k<<<(int)(((size_t)B_*H_*S_*S_)/256), 256>>>(Sc);
    sgemm_k<<<dim3(2, 16, B_*H_), 256>>>(Sc, V, Y, S_, DV_, S_,
        (long long)S_*S_, (long long)S_*DV_, (long long)S_*DV_, 1, B_*H_);

    // 5) groupnorm + silu gate
    gnorm_gate_k<<<B_*S_*H_, 256>>>(Y, G, gn_w, gn_b, gated);

    // 6) output projection + residual
    sgemm_k<<<dim3(8, 32, 1), 256>>>(gated, W_O, X2, NT_, D_, VD_, 0, 0, 0, 1, 1);
    add_k<<<(NT_*D_)/256, 256>>>(X2, X, (size_t)NT_*D_);

    // 7) ln2 + FFN (exact gelu) + residual
    layernorm_k<<<NT_, 256>>>(X2, ln2_w, ln2_b, Xn);
    sgemm_k<<<dim3(32, 32, 1), 256>>>(Xn, ffn_w1, h1, NT_, FFN_, D_, 0, 0, 0, 1, 1);
    biasgelu_k<<<(int)(((size_t)NT_*FFN_)/256), 256>>>(h1, ffn_b1);
    sgemm_k<<<dim3(8, 32, 1), 256>>>(h1, ffn_w2, out, NT_, D_, FFN_, 0, 0, 0, 1, 1);
    final_k<<<(NT_*D_)/256, 256>>>(out, ffn_b2, X2);
}